// round 3
// baseline (speedup 1.0000x reference)
#include <cuda_runtime.h>

#define NCHAN 256
#define NPTS  49

// HWC scratch for image 0 of each pyramid level.
// sizes (pixels): L2=65536, L3=16384, L4=4096, L5=1024  -> total 87040 px * 256 ch
#define OFF_L2 0
#define OFF_L3 (65536 * 256)
#define OFF_L4 (OFF_L3 + 16384 * 256)
#define OFF_L5 (OFF_L4 + 4096 * 256)
#define SCRATCH_ELEMS (OFF_L5 + 1024 * 256)

__device__ float g_scratch[SCRATCH_ELEMS];

// ---- CHW -> HWC transpose, 32x32 tiles, coalesced both sides ----
__global__ __launch_bounds__(256) void tpose(const float* __restrict__ in,
                                             float* __restrict__ op, int HW) {
    __shared__ float tile[32][33];
    int x     = blockIdx.x * 32 + threadIdx.x;  // pixel
    int cbase = blockIdx.y * 32;                // channel base
    #pragma unroll
    for (int j = threadIdx.y; j < 32; j += 8)
        tile[j][threadIdx.x] = in[(cbase + j) * HW + x];
    __syncthreads();
    int pbase = blockIdx.x * 32;
    #pragma unroll
    for (int j = threadIdx.y; j < 32; j += 8)
        op[(pbase + j) * NCHAN + cbase + threadIdx.x] = tile[threadIdx.x][j];
}

// ---- pooling from HWC scratch: dense 128B gathers ----
__global__ __launch_bounds__(512) void roi_pool(const float* __restrict__ rois,
                                                float* __restrict__ out) {
    __shared__ int   s_oTL[NPTS], s_oTR[NPTS], s_oBL[NPTS], s_oBR[NPTS];
    __shared__ float s_lx[NPTS], s_ly[NPTS], s_m[NPTS];
    __shared__ float sout[128 * NPTS];   // one channel-phase of outputs

    int n   = blockIdx.x;
    int tid = threadIdx.x;

    // ---- per-roi params (uniform; every thread computes level cheaply) ----
    float rx1 = __ldg(rois + 4 * n + 0);
    float ry1 = __ldg(rois + 4 * n + 1);
    float rx2 = __ldg(rois + 4 * n + 2);
    float ry2 = __ldg(rois + 4 * n + 3);

    float area = (ry2 - ry1) * (rx2 - rx1);
    float lvlf = log2f(sqrtf(fmaxf(area, 0.0f)) / 224.0f);
    int level = (int)rintf(lvlf) + 4;          // half-even, matches jnp.round
    level = min(5, max(2, level));

    int W = 1024 >> level;                     // H == W
    const float* fm = g_scratch +
        ((level == 2) ? OFF_L2 : (level == 3) ? OFF_L3 : (level == 4) ? OFF_L4 : OFF_L5);

    if (tid < NPTS) {
        float scale = (float)(W - 1);
        float ny1 = ry1 * (1.0f / 1024.0f);
        float nx1 = rx1 * (1.0f / 1024.0f);
        float dy  = __fsub_rn(ry2 * (1.0f / 1024.0f), ny1);
        float dx  = __fsub_rn(rx2 * (1.0f / 1024.0f), nx1);

        int py = tid / 7;
        int px = tid - py * 7;

        float ty = (float)py / 6.0f;
        float ys = __fmul_rn(__fadd_rn(ny1, __fmul_rn(ty, dy)), scale);
        bool  vy = (ys >= 0.0f) && (ys <= scale);
        float ysc = fminf(fmaxf(ys, 0.0f), scale);
        int   y0  = (int)floorf(ysc);
        int   y1i = min(y0 + 1, W - 1);
        float ly  = __fsub_rn(ysc, (float)y0);

        float tx = (float)px / 6.0f;
        float xs = __fmul_rn(__fadd_rn(nx1, __fmul_rn(tx, dx)), scale);
        bool  vx = (xs >= 0.0f) && (xs <= scale);
        float xsc = fminf(fmaxf(xs, 0.0f), scale);
        int   x0  = (int)floorf(xsc);
        int   x1i = min(x0 + 1, W - 1);
        float lx  = __fsub_rn(xsc, (float)x0);

        s_oTL[tid] = (y0  * W + x0 ) * NCHAN;
        s_oTR[tid] = (y0  * W + x1i) * NCHAN;
        s_oBL[tid] = (y1i * W + x0 ) * NCHAN;
        s_oBR[tid] = (y1i * W + x1i) * NCHAN;
        s_lx[tid] = lx;
        s_ly[tid] = ly;
        s_m[tid]  = (vy && vx) ? 1.0f : 0.0f;
    }
    __syncthreads();

    int warpid = tid >> 5;
    int lane   = tid & 31;
    long obase = (long)n * (NCHAN * NPTS);

    #pragma unroll
    for (int phase = 0; phase < 2; phase++) {
        // 196 warp-tasks: (pt 0..48) x (cg 0..3); channel = phase*128 + cg*32 + lane
        for (int t = warpid; t < NPTS * 4; t += 16) {
            int pt = t >> 2;
            int cg = t & 3;
            int c_local = cg * 32 + lane;
            int c = phase * 128 + c_local;

            const float* base = fm + c;
            float tl = __ldg(base + s_oTL[pt]);
            float tr = __ldg(base + s_oTR[pt]);
            float bl = __ldg(base + s_oBL[pt]);
            float br = __ldg(base + s_oBR[pt]);

            float lx = s_lx[pt], ly = s_ly[pt], m = s_m[pt];
            float top = fmaf(tr - tl, lx, tl);
            float bot = fmaf(br - bl, lx, bl);
            float v   = fmaf(bot - top, ly, top) * m;
            sout[c_local * NPTS + pt] = v;   // stride 49: conflict-free
        }
        __syncthreads();
        for (int i = tid; i < 128 * NPTS; i += 512)
            out[obase + phase * (128 * NPTS) + i] = sout[i];
        __syncthreads();
    }
}

extern "C" void kernel_launch(void* const* d_in, const int* in_sizes, int n_in,
                              void* d_out, int out_size) {
    const float* p2   = (const float*)d_in[0];
    const float* p3   = (const float*)d_in[1];
    const float* p4   = (const float*)d_in[2];
    const float* p5   = (const float*)d_in[3];
    const float* rois = (const float*)d_in[4];
    float* out = (float*)d_out;

    float* scratch;
    cudaGetSymbolAddress((void**)&scratch, g_scratch);

    dim3 tb(32, 8);
    tpose<<<dim3(65536 / 32, 8), tb>>>(p2, scratch + OFF_L2, 65536);
    tpose<<<dim3(16384 / 32, 8), tb>>>(p3, scratch + OFF_L3, 16384);
    tpose<<<dim3( 4096 / 32, 8), tb>>>(p4, scratch + OFF_L4,  4096);
    tpose<<<dim3( 1024 / 32, 8), tb>>>(p5, scratch + OFF_L5,  1024);

    int nrois = in_sizes[4] / 4;   // B*R
    roi_pool<<<nrois, 512>>>(rois, out);
}

// round 4
// speedup vs baseline: 1.7524x; 1.7524x over previous
#include <cuda_runtime.h>

#define NCHAN 256
#define NPTS  49

// HWC scratch for image 0, levels 3..5 only (level 2 is pooled directly from NCHW p2)
#define OFF_L3 0
#define OFF_L4 (16384 * 256)
#define OFF_L5 (OFF_L4 + 4096 * 256)
#define SCRATCH_ELEMS (OFF_L5 + 1024 * 256)
__device__ float g_scratch[SCRATCH_ELEMS];

// ---- fused CHW->HWC transpose for levels 3,4,5 (image 0 only) ----
// blocks: L3 = 512*8 = 4096, L4 = 128*8 = 1024, L5 = 32*8 = 256  -> 5376 total
__global__ __launch_bounds__(256) void tpose_all(const float* __restrict__ p3,
                                                 const float* __restrict__ p4,
                                                 const float* __restrict__ p5) {
    __shared__ float tile[32][33];
    int b = blockIdx.x;
    const float* in;
    float* op;
    int HW;
    if (b < 4096)      { in = p3; op = g_scratch + OFF_L3; HW = 16384; }
    else if (b < 5120) { b -= 4096; in = p4; op = g_scratch + OFF_L4; HW = 4096; }
    else               { b -= 5120; in = p5; op = g_scratch + OFF_L5; HW = 1024; }
    int xt = b >> 3;         // pixel tile
    int cbase = (b & 7) * 32; // channel tile

    int x = xt * 32 + threadIdx.x;
    #pragma unroll
    for (int j = threadIdx.y; j < 32; j += 8)
        tile[j][threadIdx.x] = __ldcs(in + (cbase + j) * HW + x);
    __syncthreads();
    int pbase = xt * 32;
    #pragma unroll
    for (int j = threadIdx.y; j < 32; j += 8)
        op[(pbase + j) * NCHAN + cbase + threadIdx.x] = tile[threadIdx.x][j];
}

// ---- pooling: HWC dense gathers for levels 3-5, NCHW direct path for level 2 ----
__global__ __launch_bounds__(256) void roi_pool(const float* __restrict__ p2,
                                                const float* __restrict__ rois,
                                                float* __restrict__ out) {
    __shared__ int   s_oTL[NPTS], s_oTR[NPTS], s_oBL[NPTS], s_oBR[NPTS];
    __shared__ float s_lx[NPTS], s_ly[NPTS], s_m[NPTS];
    __shared__ float sout[128 * NPTS];

    int n   = blockIdx.x;
    int tid = threadIdx.x;

    float rx1 = __ldg(rois + 4 * n + 0);
    float ry1 = __ldg(rois + 4 * n + 1);
    float rx2 = __ldg(rois + 4 * n + 2);
    float ry2 = __ldg(rois + 4 * n + 3);

    float area = (ry2 - ry1) * (rx2 - rx1);
    float lvlf = log2f(sqrtf(fmaxf(area, 0.0f)) / 224.0f);
    int level = (int)rintf(lvlf) + 4;          // half-even, matches jnp.round
    level = min(5, max(2, level));
    int W = 1024 >> level;                     // H == W

    if (tid < NPTS) {
        float scale = (float)(W - 1);
        float ny1 = ry1 * (1.0f / 1024.0f);
        float nx1 = rx1 * (1.0f / 1024.0f);
        float dy  = __fsub_rn(ry2 * (1.0f / 1024.0f), ny1);
        float dx  = __fsub_rn(rx2 * (1.0f / 1024.0f), nx1);

        int py = tid / 7;
        int px = tid - py * 7;

        float ty = (float)py / 6.0f;
        float ys = __fmul_rn(__fadd_rn(ny1, __fmul_rn(ty, dy)), scale);
        bool  vy = (ys >= 0.0f) && (ys <= scale);
        float ysc = fminf(fmaxf(ys, 0.0f), scale);
        int   y0  = (int)floorf(ysc);
        int   y1i = min(y0 + 1, W - 1);
        float ly  = __fsub_rn(ysc, (float)y0);

        float tx = (float)px / 6.0f;
        float xs = __fmul_rn(__fadd_rn(nx1, __fmul_rn(tx, dx)), scale);
        bool  vx = (xs >= 0.0f) && (xs <= scale);
        float xsc = fminf(fmaxf(xs, 0.0f), scale);
        int   x0  = (int)floorf(xsc);
        int   x1i = min(x0 + 1, W - 1);
        float lx  = __fsub_rn(xsc, (float)x0);

        // plain pixel offsets (y*W + x); scaled per path below
        s_oTL[tid] = y0  * W + x0;
        s_oTR[tid] = y0  * W + x1i;
        s_oBL[tid] = y1i * W + x0;
        s_oBR[tid] = y1i * W + x1i;
        s_lx[tid] = lx;
        s_ly[tid] = ly;
        s_m[tid]  = (vy && vx) ? 1.0f : 0.0f;
    }
    __syncthreads();

    long obase = (long)n * (NCHAN * NPTS);

    if (level >= 3) {
        const float* fm = g_scratch +
            ((level == 3) ? OFF_L3 : (level == 4) ? OFF_L4 : OFF_L5);
        int warpid = tid >> 5;
        int lane   = tid & 31;

        #pragma unroll
        for (int phase = 0; phase < 2; phase++) {
            for (int pt = warpid; pt < NPTS; pt += 8) {
                int oTL = s_oTL[pt] * NCHAN + lane + phase * 128;
                int oTR = s_oTR[pt] * NCHAN + lane + phase * 128;
                int oBL = s_oBL[pt] * NCHAN + lane + phase * 128;
                int oBR = s_oBR[pt] * NCHAN + lane + phase * 128;
                float lx = s_lx[pt], ly = s_ly[pt], m = s_m[pt];

                float tl[4], tr[4], bl[4], br[4];
                #pragma unroll
                for (int cg = 0; cg < 4; cg++) {
                    int c = cg * 32;
                    tl[cg] = __ldg(fm + oTL + c);
                    tr[cg] = __ldg(fm + oTR + c);
                    bl[cg] = __ldg(fm + oBL + c);
                    br[cg] = __ldg(fm + oBR + c);
                }
                #pragma unroll
                for (int cg = 0; cg < 4; cg++) {
                    float top = fmaf(tr[cg] - tl[cg], lx, tl[cg]);
                    float bot = fmaf(br[cg] - bl[cg], lx, bl[cg]);
                    sout[(cg * 32 + lane) * NPTS + pt] = fmaf(bot - top, ly, top) * m;
                }
            }
            __syncthreads();
            for (int i = tid; i < 128 * NPTS; i += 256)
                __stcs(&out[obase + phase * (128 * NPTS) + i], sout[i]);
            __syncthreads();
        }
    } else {
        // level 2: gather directly from NCHW p2 (image 0, plane 65536, W=256)
        int pt = tid & 63;   // 49 active
        int cg = tid >> 6;   // 0..3
        if (pt < NPTS) {
            int oTL = s_oTL[pt], oTR = s_oTR[pt], oBL = s_oBL[pt], oBR = s_oBR[pt];
            float lx = s_lx[pt], ly = s_ly[pt], m = s_m[pt];
            #pragma unroll 4
            for (int c = cg; c < NCHAN; c += 4) {
                const float* fc = p2 + c * 65536;
                float tl = __ldg(fc + oTL);
                float tr = __ldg(fc + oTR);
                float bl = __ldg(fc + oBL);
                float br = __ldg(fc + oBR);
                float top = fmaf(tr - tl, lx, tl);
                float bot = fmaf(br - bl, lx, bl);
                __stcs(&out[obase + (long)c * NPTS + pt], fmaf(bot - top, ly, top) * m);
            }
        }
    }
}

extern "C" void kernel_launch(void* const* d_in, const int* in_sizes, int n_in,
                              void* d_out, int out_size) {
    const float* p2   = (const float*)d_in[0];
    const float* p3   = (const float*)d_in[1];
    const float* p4   = (const float*)d_in[2];
    const float* p5   = (const float*)d_in[3];
    const float* rois = (const float*)d_in[4];
    float* out = (float*)d_out;

    tpose_all<<<5376, dim3(32, 8)>>>(p3, p4, p5);

    int nrois = in_sizes[4] / 4;   // B*R
    roi_pool<<<nrois, 256>>>(p2, rois, out);
}